// round 14
// baseline (speedup 1.0000x reference)
#include <cuda_runtime.h>
#include <cuda_bf16.h>
#include <math.h>

#define BS 16
#define HDIM 2048
#define QL 768
#define KVL 512
#define DR 64
#define DN 128
#define NH 16
#define NIH 8
#define IDXD 128
#define BLKSZ 128
#define BPS 32
#define MAXKV 4096
#define TOPK 1024
#define NSPLIT 16
#define SPLITROWS 64

#define NZ1 32          /* stage1 K-slices of 64 */
#define NZ2 12          /* stage2 K-slices of 64 */
#define T1DIM 1472
#define T2DIM 4104

#define ATT_SCALE 0.07216878364870323f
#define IDX_SCALE 0.08838834764831845f

#define NBMAX 448
#define SMSZ 57344

typedef unsigned long long ull;

__device__ __forceinline__ ull ffma2(ull a, ull b, ull c) {
    ull d; asm("fma.rn.f32x2 %0, %1, %2, %3;" : "=l"(d) : "l"(a), "l"(b), "l"(c)); return d;
}
__device__ __forceinline__ ull fmul2(ull a, ull b) {
    ull d; asm("mul.rn.f32x2 %0, %1, %2;" : "=l"(d) : "l"(a), "l"(b)); return d;
}
__device__ __forceinline__ ull fpack2(float lo, float hi) {
    ull d; asm("mov.b64 %0, {%1, %2};" : "=l"(d) : "f"(lo), "f"(hi)); return d;
}
__device__ __forceinline__ float2 funpack2(ull v) {
    float lo, hi; asm("mov.b64 {%0, %1}, %2;" : "=f"(lo), "=f"(hi) : "l"(v)); return make_float2(lo, hi);
}

// ---------------- scratch ----------------
__device__ float g_t1p[NZ1][BS][T1DIM];
__device__ float g_t2p[NZ2][BS][T2DIM];
__device__ float g_cq[BS][QL];
__device__ float g_ckv[BS][KVL];
__device__ float g_kr[BS][DR];
__device__ float g_ki[BS][IDXD];
__device__ float g_q[BS][NH * 192];
__device__ float g_qi[BS][NIH * IDXD];
__device__ float g_hw[BS][NIH];
__device__ float g_qpe[BS][NH][DR];
__device__ float g_qlat[BS][NH][KVL];
__device__ float g_isc[BS][MAXKV];
__device__ int   g_sel[BS][TOPK];
__device__ float g_selval[BS][TOPK];
__device__ float g_m[BS][NSPLIT][NH];
__device__ float g_l[BS][NSPLIT][NH];
__device__ float g_op[BS][NSPLIT][NH][KVL];

__device__ unsigned g_barcnt[8];
__device__ unsigned g_ack;

__device__ __forceinline__ void gsync(int id, int nb) {
    __syncthreads();
    if (threadIdx.x == 0) {
        __threadfence();
        atomicAdd(&g_barcnt[id], 1u);
        while (*(volatile unsigned*)&g_barcnt[id] < (unsigned)nb) { __nanosleep(64); }
    }
    __syncthreads();
}

__device__ __forceinline__ float blockSum256(float v, float* buf) {
    int tid = threadIdx.x;
    buf[tid] = v;
    __syncthreads();
    for (int s = 128; s > 0; s >>= 1) {
        if (tid < s) buf[tid] += buf[tid + s];
        __syncthreads();
    }
    float r = buf[0];
    __syncthreads();
    return r;
}

__global__ void __launch_bounds__(256, 3)
k_mega(const float* __restrict__ x, const float* __restrict__ w_dq,
       const float* __restrict__ w_uq_qr, const float* __restrict__ w_uk,
       const float* __restrict__ w_dkv, const float* __restrict__ gamma_cq,
       const float* __restrict__ gamma_ckv, const float* __restrict__ sinp,
       const float* __restrict__ cosp, const int* __restrict__ cidx,
       const float* __restrict__ kvc, const float* __restrict__ krc,
       const int* __restrict__ bt, const int* __restrict__ act_seqs,
       const float* __restrict__ w_idx_qb, const float* __restrict__ w_idxk,
       const float* __restrict__ w_idx_proj, const float* __restrict__ in_g,
       const float* __restrict__ in_b, const float* __restrict__ ikc,
       float* __restrict__ out, int nb)
{
    extern __shared__ __align__(16) char sm_raw[];
    int tid = threadIdx.x;
    int bx = blockIdx.x;

    // ===== P0: stage1 partials, 8 batches/unit, transposed smem [k][b], FFMA2 =====
    {
        float* s_x = (float*)sm_raw;   // [64][8]
        for (int u = bx; u < 6 * 2 * NZ1; u += nb) {
            int cx = u % 6, bg = (u / 6) & 1, z = u / 12;
            int i0 = z * 64, b0 = bg * 8;
            for (int idx = tid; idx < 512; idx += 256) {
                int i = idx >> 3, b = idx & 7;
                s_x[idx] = x[(b0 + b) * HDIM + i0 + i];
            }
            __syncthreads();
            int col = cx * 256 + tid;
            if (col < T1DIM) {
                const float* W; int stride, c;
                if (col < QL)                 { W = w_dq;   stride = QL;       c = col; }
                else if (col < QL + KVL + DR) { W = w_dkv;  stride = KVL + DR; c = col - QL; }
                else                          { W = w_idxk; stride = IDXD;     c = col - (QL + KVL + DR); }
                const float* wp = W + (size_t)i0 * stride + c;
                ull acc2[4];
                #pragma unroll
                for (int b = 0; b < 4; b++) acc2[b] = 0ull;
                #pragma unroll 8
                for (int i = 0; i < 64; i++) {
                    float w = wp[(size_t)i * stride];
                    ull ww = fpack2(w, w);
                    ulonglong2 xa = *(const ulonglong2*)&s_x[i * 8 + 0];
                    ulonglong2 xb = *(const ulonglong2*)&s_x[i * 8 + 4];
                    acc2[0] = ffma2(xa.x, ww, acc2[0]);
                    acc2[1] = ffma2(xa.y, ww, acc2[1]);
                    acc2[2] = ffma2(xb.x, ww, acc2[2]);
                    acc2[3] = ffma2(xb.y, ww, acc2[3]);
                }
                #pragma unroll
                for (int b = 0; b < 4; b++) {
                    float2 t = funpack2(acc2[b]);
                    g_t1p[z][b0 + 2 * b][col]     = t.x;
                    g_t1p[z][b0 + 2 * b + 1][col] = t.y;
                }
            }
            __syncthreads();
        }
    }
    gsync(0, nb);

    // ===== P1: norms + rope(kr) =====
    {
        float* s_t  = (float*)sm_raw;
        float* sred = (float*)(sm_raw + T1DIM * 4 + 64);
        for (int u = bx; u < BS; u += nb) {
            int b = u;
            for (int i = tid; i < T1DIM; i += 256) {
                float a = 0.f;
                #pragma unroll
                for (int z = 0; z < NZ1; z++) a += g_t1p[z][b][i];
                s_t[i] = a;
            }
            __syncthreads();
            float ss = 0.f;
            for (int i = tid; i < QL; i += 256) ss += s_t[i] * s_t[i];
            ss = blockSum256(ss, sred);
            float r = rsqrtf(ss / (float)QL + 1e-6f);
            for (int i = tid; i < QL; i += 256) g_cq[b][i] = s_t[i] * r * gamma_cq[i];
            float s2 = 0.f;
            for (int i = tid; i < KVL; i += 256) { float v = s_t[QL + i]; s2 += v * v; }
            s2 = blockSum256(s2, sred);
            float r2 = rsqrtf(s2 / (float)KVL + 1e-6f);
            for (int i = tid; i < KVL; i += 256) g_ckv[b][i] = s_t[QL + i] * r2 * gamma_ckv[i];
            if (tid < DR) {
                int d = tid;
                float v = s_t[QL + KVL + d];
                float rot = (d < 32) ? -s_t[QL + KVL + d + 32] : s_t[QL + KVL + d - 32];
                g_kr[b][d] = v * cosp[b * DR + d] + rot * sinp[b * DR + d];
            }
            float sm = 0.f;
            for (int i = tid; i < IDXD; i += 256) sm += s_t[QL + KVL + DR + i];
            sm = blockSum256(sm, sred);
            float mean = sm / (float)IDXD;
            float sv = 0.f;
            for (int i = tid; i < IDXD; i += 256) { float c = s_t[QL + KVL + DR + i] - mean; sv += c * c; }
            sv = blockSum256(sv, sred);
            float rv = rsqrtf(sv / (float)IDXD + 1e-6f);
            for (int i = tid; i < IDXD; i += 256) {
                float c = s_t[QL + KVL + DR + i] - mean;
                g_ki[b][i] = c * rv * in_g[i] + in_b[i];
            }
            __syncthreads();
        }
    }
    gsync(1, nb);

    // ===== P2: stage2 partials, 8 batches/unit, transposed smem, FFMA2 =====
    {
        float* s_cq = (float*)sm_raw;   // [64][8]
        for (int u = bx; u < 17 * 2 * NZ2; u += nb) {
            int cx = u % 17, bg = (u / 17) & 1, z = u / 34;
            int i0 = z * 64, b0 = bg * 8;
            for (int idx = tid; idx < 512; idx += 256) {
                int i = idx >> 3, b = idx & 7;
                s_cq[idx] = g_cq[b0 + b][i0 + i];
            }
            __syncthreads();
            int col = cx * 256 + tid;
            if (col < T2DIM) {
                const float* W; int stride, c;
                if (col < 3072)      { W = w_uq_qr;    stride = 3072; c = col; }
                else if (col < 4096) { W = w_idx_qb;   stride = 1024; c = col - 3072; }
                else                 { W = w_idx_proj; stride = 8;    c = col - 4096; }
                const float* wp = W + (size_t)i0 * stride + c;
                ull acc2[4];
                #pragma unroll
                for (int b = 0; b < 4; b++) acc2[b] = 0ull;
                #pragma unroll 8
                for (int i = 0; i < 64; i++) {
                    float w = wp[(size_t)i * stride];
                    ull ww = fpack2(w, w);
                    ulonglong2 xa = *(const ulonglong2*)&s_cq[i * 8 + 0];
                    ulonglong2 xb = *(const ulonglong2*)&s_cq[i * 8 + 4];
                    acc2[0] = ffma2(xa.x, ww, acc2[0]);
                    acc2[1] = ffma2(xa.y, ww, acc2[1]);
                    acc2[2] = ffma2(xb.x, ww, acc2[2]);
                    acc2[3] = ffma2(xb.y, ww, acc2[3]);
                }
                #pragma unroll
                for (int b = 0; b < 4; b++) {
                    float2 t = funpack2(acc2[b]);
                    g_t2p[z][b0 + 2 * b][col]     = t.x;
                    g_t2p[z][b0 + 2 * b + 1][col] = t.y;
                }
            }
            __syncthreads();
        }
    }
    gsync(2, nb);

    // ===== P2b: reduce stage2 partials =====
    {
        int total = BS * T2DIM;
        for (int idx = bx * 256 + tid; idx < total; idx += nb * 256) {
            int b = idx / T2DIM, col = idx % T2DIM;
            float a = 0.f;
            #pragma unroll
            for (int z = 0; z < NZ2; z++) a += g_t2p[z][b][col];
            if (col < 3072)      g_q[b][col] = a;
            else if (col < 4096) g_qi[b][col - 3072] = a;
            else                 g_hw[b][col - 4096] = a;
        }
    }
    gsync(3, nb);

    // ===== P3: iscore (512 units) =====
    {
        float* s_qi = (float*)sm_raw;
        float* s_hw = (float*)(sm_raw + 4096);
        for (int u = bx; u < 512; u += nb) {
            int chunk = u & 31, b = u >> 5;
            for (int i = tid; i < NIH * IDXD; i += 256) s_qi[i] = g_qi[b][i];
            if (tid < NIH) s_hw[tid] = g_hw[b][tid];
            __syncthreads();
            int warp = tid >> 5, lane = tid & 31;
            int act = act_seqs[b];
            int ci = cidx[b];
            for (int r = warp; r < 128; r += 8) {
                int n = chunk * 128 + r;
                if (n >= act) { if (lane == 0) g_isc[b][n] = -1e9f; continue; }
                int blk = bt[b * BPS + (n >> 7)];
                long flat = (long)blk * BLKSZ + (n & 127);
                const float* kr = (flat == (long)ci) ? g_ki[b] : ikc + flat * IDXD;
                float4 kv = *(const float4*)(kr + lane * 4);
                float acc[NIH];
                #pragma unroll
                for (int h = 0; h < NIH; h++) {
                    float4 q = *(const float4*)&s_qi[h * IDXD + lane * 4];
                    acc[h] = kv.x * q.x + kv.y * q.y + kv.z * q.z + kv.w * q.w;
                }
                #pragma unroll
                for (int off = 16; off; off >>= 1) {
                    #pragma unroll
                    for (int h = 0; h < NIH; h++)
                        acc[h] += __shfl_xor_sync(0xffffffffu, acc[h], off);
                }
                if (lane == 0) {
                    float s = 0.f;
                    #pragma unroll
                    for (int h = 0; h < NIH; h++) s += s_hw[h] * fmaxf(acc[h], 0.f);
                    g_isc[b][n] = s * IDX_SCALE;
                }
            }
            __syncthreads();
        }
    }
    gsync(4, nb);

    // ===== P4: topk (16 units) + qprep (64 units) overlapped =====
    {
        for (int u = bx; u < 16 + 64; u += nb) {
            if (u < 16) {
                unsigned* s_key  = (unsigned*)sm_raw;
                unsigned* s_hist = (unsigned*)(sm_raw + 16384);
                unsigned* s_scan = (unsigned*)(sm_raw + 17408);
                unsigned* s_bm   = (unsigned*)(sm_raw + 18432);
                unsigned* s_cnt  = (unsigned*)(sm_raw + 18944);
                unsigned* s_pref = (unsigned*)(sm_raw + 18948);
                int*      s_rem  = (int*)(sm_raw + 18952);
                int*      s_Bw   = (int*)(sm_raw + 18956);
                int*      s_need = (int*)(sm_raw + 18960);
                int b = u;
                int act = act_seqs[b];
                for (int i = tid; i < MAXKV; i += 256) {
                    float v = (i < act) ? g_isc[b][i] : -1e9f;
                    unsigned uu = __float_as_uint(v);
                    uu = (uu & 0x80000000u) ? ~uu : (uu | 0x80000000u);
                    s_key[i] = uu;
                }
                if (tid == 0) { *s_cnt = 0; *s_rem = TOPK; *s_pref = 0; }
                __syncthreads();
                for (int level = 0; level < 4; level++) {
                    int shift = 24 - level * 8;
                    s_hist[tid] = 0;
                    __syncthreads();
                    unsigned pref = *s_pref;
                    for (int i = tid; i < MAXKV; i += 256) {
                        unsigned uu = s_key[i];
                        if (level == 0 || (uu >> (shift + 8)) == pref)
                            atomicAdd(&s_hist[(uu >> shift) & 255u], 1u);
                    }
                    __syncthreads();
                    s_scan[tid] = s_hist[tid];
                    __syncthreads();
                    #pragma unroll
                    for (int off = 1; off < 256; off <<= 1) {
                        unsigned t = (tid + off < 256) ? s_scan[tid + off] : 0u;
                        __syncthreads();
                        s_scan[tid] += t;
                        __syncthreads();
                    }
                    int rem = *s_rem;
                    unsigned cumGT = s_scan[tid] - s_hist[tid];
                    if ((int)cumGT < rem && (int)s_scan[tid] >= rem) {
                        *s_pref = (pref << 8) | (unsigned)tid;
                        *s_rem = rem - (int)cumGT;
                    }
                    __syncthreads();
                }
                unsigned K = *s_pref;
                for (int i = tid; i < MAXKV; i += 256) {
                    if (s_key[i] > K) {
                        unsigned pos = atomicAdd(s_cnt, 1u);
                        g_sel[b][pos] = i;
                        g_selval[b][pos] = (i < act) ? g_isc[b][i] : -1e9f;
                    }
                }
                for (int w = tid; w < MAXKV / 32; w += 256) s_bm[w] = 0;
                __syncthreads();
                for (int i = tid; i < MAXKV; i += 256)
                    if (s_key[i] == K) atomicOr(&s_bm[i >> 5], 1u << (i & 31));
                __syncthreads();
                if (tid == 0) {
                    int need = *s_rem;
                    int w = 0;
                    for (; w < MAXKV / 32; w++) {
                        int pc = __popc(s_bm[w]);
                        if (pc >= need) break;
                        need -= pc;
                    }
                    *s_Bw = w; *s_need = need;
                }
                __syncthreads();
                int Bw = *s_Bw, need = *s_need;
                for (int i = tid; i < MAXKV; i += 256) {
                    if (s_key[i] == K) {
                        int w = i >> 5, bit = i & 31;
                        bool take = (w < Bw) ||
                                    (w == Bw && (int)__popc(s_bm[w] & ((1u << bit) - 1u)) < need);
                        if (take) {
                            unsigned pos = atomicAdd(s_cnt, 1u);
                            g_sel[b][pos] = i;
                            g_selval[b][pos] = (i < act) ? g_isc[b][i] : -1e9f;
                        }
                    }
                }
                __syncthreads();
            } else {
                int u2 = u - 16;
                int h = u2 & 15, r = u2 >> 4;
                int cc = r & 1, bg = r >> 1;
                int b0 = bg * 8;
                float* s_qn = (float*)sm_raw;  // [128][8] transposed
                for (int idx = tid; idx < 1024; idx += 256) {
                    int d = idx >> 3, bb = idx & 7;
                    s_qn[idx] = g_q[b0 + bb][h * 192 + d];
                }
                if (cc == 0) {
                    for (int idx = tid; idx < 512; idx += 256) {
                        int bb = idx >> 6, d = idx & 63;
                        int b = b0 + bb;
                        float v = g_q[b][h * 192 + DN + d];
                        float rot = (d < 32) ? -g_q[b][h * 192 + DN + d + 32] : g_q[b][h * 192 + DN + d - 32];
                        g_qpe[b][h][d] = v * cosp[b * DR + d] + rot * sinp[b * DR + d];
                    }
                }
                __syncthreads();
                int c = cc * 256 + tid;
                const float* wk = w_uk + (size_t)h * DN * KVL + c;
                ull acc2[4];
                #pragma unroll
                for (int b = 0; b < 4; b++) acc2[b] = 0ull;
                #pragma unroll 8
                for (int d = 0; d < DN; d++) {
                    float w = wk[(size_t)d * KVL];
                    ull ww = fpack2(w, w);
                    ulonglong2 xa = *(const ulonglong2*)&s_qn[d * 8 + 0];
                    ulonglong2 xb = *(const ulonglong2*)&s_qn[d * 8 + 4];
                    acc2[0] = ffma2(xa.x, ww, acc2[0]);
                    acc2[1] = ffma2(xa.y, ww, acc2[1]);
                    acc2[2] = ffma2(xb.x, ww, acc2[2]);
                    acc2[3] = ffma2(xb.y, ww, acc2[3]);
                }
                #pragma unroll
                for (int b = 0; b < 4; b++) {
                    float2 t = funpack2(acc2[b]);
                    g_qlat[b0 + 2 * b][h][c]     = t.x;
                    g_qlat[b0 + 2 * b + 1][h][c] = t.y;
                }
                __syncthreads();
            }
        }
    }
    gsync(5, nb);

    // ===== P5: attention partials — online softmax, smem-staged KV, FFMA2 (256 units) =====
    {
        float* s_qlat = (float*)sm_raw;                       // 32768 B
        float* s_qpe  = (float*)(sm_raw + 32768);             //  4096 B
        float* s_kv   = (float*)(sm_raw + 36864);             // 16384 B (8 rows x 512)
        float* s_kr   = (float*)(sm_raw + 53248);             //  2048 B (8 rows x 64)
        float* s_sc   = (float*)(sm_raw + 55296);             //   512 B (8 x 16)
        float* s_m    = (float*)(sm_raw + 55808);
        float* s_l    = (float*)(sm_raw + 55872);
        float* s_fac  = (float*)(sm_raw + 55936);
        const float** s_ckvp = (const float**)(sm_raw + 56064);
        const float** s_krp  = (const float**)(sm_raw + 56576);
        int* s_vld = (int*)(sm_raw + 57088);
        for (int u = bx; u < NSPLIT * BS; u += nb) {
            int s = u & 15, b = u >> 4;
            const float4* qlb = (const float4*)&g_qlat[b][0][0];
            for (int i = tid; i < NH * KVL / 4; i += 256) ((float4*)s_qlat)[i] = qlb[i];
            const float4* qpb = (const float4*)&g_qpe[b][0][0];
            for (int i = tid; i < NH * DR / 4; i += 256) ((float4*)s_qpe)[i] = qpb[i];
            if (tid < SPLITROWS) {
                int j = tid;
                int n = g_sel[b][s * SPLITROWS + j];
                float v = g_selval[b][s * SPLITROWS + j];
                bool valid = v > -1e8f;
                const float* cp; const float* kp;
                if (!valid) { cp = g_ckv[b]; kp = g_kr[b]; }
                else {
                    int blk = bt[b * BPS + (n >> 7)];
                    long flat = (long)blk * BLKSZ + (n & 127);
                    if (flat == (long)cidx[b]) { cp = g_ckv[b]; kp = g_kr[b]; }
                    else { cp = kvc + flat * KVL; kp = krc + flat * DR; }
                }
                s_ckvp[j] = cp; s_krp[j] = kp; s_vld[j] = valid ? 1 : 0;
            }
            if (tid < NH) { s_m[tid] = -1e30f; s_l[tid] = 0.f; }
            // o accumulators: head-paired f32x2; oc0 = column tid, oc1 = column tid+256
            ull oc0[NH / 2], oc1[NH / 2];
            #pragma unroll
            for (int k = 0; k < NH / 2; k++) { oc0[k] = 0ull; oc1[k] = 0ull; }
            __syncthreads();
            int warp = tid >> 5, lane = tid & 31;
            for (int g = 0; g < SPLITROWS / 8; g++) {
                #pragma unroll
                for (int k = 0; k < 4; k++) {
                    int f = tid + 256 * k;
                    int r = f >> 7, pos = f & 127;
                    ((float4*)&s_kv[r * 512])[pos] = ((const float4*)s_ckvp[g * 8 + r])[pos];
                }
                if (tid < 128) {
                    int r = tid >> 4, pos = tid & 15;
                    ((float4*)&s_kr[r * 64])[pos] = ((const float4*)s_krp[g * 8 + r])[pos];
                }
                __syncthreads();
                {
                    int j = warp;
                    ull acc2[NH];
                    #pragma unroll
                    for (int h = 0; h < NH; h++) acc2[h] = 0ull;
                    #pragma unroll
                    for (int q = 0; q < 4; q++) {
                        ulonglong2 v = *(const ulonglong2*)&s_kv[j * 512 + 4 * (lane + 32 * q)];
                        #pragma unroll
                        for (int h = 0; h < NH; h++) {
                            ulonglong2 ql = *(const ulonglong2*)&s_qlat[h * KVL + 4 * (lane + 32 * q)];
                            acc2[h] = ffma2(v.x, ql.x, acc2[h]);
                            acc2[h] = ffma2(v.y, ql.y, acc2[h]);
                        }
                    }
                    ull kvr = *(const ull*)&s_kr[j * 64 + 2 * lane];
                    float acc[NH];
                    #pragma unroll
                    for (int h = 0; h < NH; h++) {
                        ull qp = *(const ull*)&s_qpe[h * DR + 2 * lane];
                        acc2[h] = ffma2(kvr, qp, acc2[h]);
                        float2 t = funpack2(acc2[h]);
                        acc[h] = t.x + t.y;
                    }
                    #pragma unroll
                    for (int off = 16; off; off >>= 1) {
                        #pragma unroll
                        for (int h = 0; h < NH; h++)
                            acc[h] += __shfl_xor_sync(0xffffffffu, acc[h], off);
                    }
                    if (lane == 0) {
                        bool valid = s_vld[g * 8 + j] != 0;
                        #pragma unroll
                        for (int h = 0; h < NH; h++)
                            s_sc[j * NH + h] = valid ? acc[h] * ATT_SCALE : -1e9f;
                    }
                }
                __syncthreads();
                #pragma unroll
                for (int hh = warp; hh < NH; hh += 8) {
                    float sc = (lane < 8) ? s_sc[lane * NH + hh] : -3.0e38f;
                    float gm = sc;
                    #pragma unroll
                    for (int off = 4; off; off >>= 1) gm = fmaxf(gm, __shfl_xor_sync(0xffffffffu, gm, off));
                    float oldm = s_m[hh];
                    float newm = fmaxf(oldm, gm);
                    float p = (lane < 8) ? __expf(sc - newm) : 0.f;
                    float sl = p;
                    #pragma unroll
                    for (int off = 4; off; off >>= 1) sl += __shfl_xor_sync(0xffffffffu, sl, off);
                    if (lane < 8) s_sc[lane * NH + hh] = p;
                    if (lane == 0) {
                        float fac = __expf(oldm - newm);
                        s_m[hh] = newm;
                        s_l[hh] = s_l[hh] * fac + sl;
                        s_fac[hh] = fac;
                    }
                }
                __syncthreads();
                {
                    // rescale with head-paired factors (free packing via reinterpret)
                    const ull* facp = (const ull*)s_fac;
                    #pragma unroll
                    for (int k = 0; k < NH / 2; k++) {
                        ull f = facp[k];
                        oc0[k] = fmul2(oc0[k], f);
                        oc1[k] = fmul2(oc1[k], f);
                    }
                    int c0 = tid, c1 = tid + 256;
                    #pragma unroll
                    for (int j = 0; j < 8; j++) {
                        float va = s_kv[j * 512 + c0];
                        float vb = s_kv[j * 512 + c1];
                        ull vva = fpack2(va, va);
                        ull vvb = fpack2(vb, vb);
                        const ull* pp = (const ull*)&s_sc[j * NH];
                        #pragma unroll
                        for (int k = 0; k < NH / 2; k++) {
                            ull p = pp[k];
                            oc0[k] = ffma2(p, vva, oc0[k]);
                            oc1[k] = ffma2(p, vvb, oc1[k]);
                        }
                    }
                }
                __syncthreads();
            }
            if (tid < NH) { g_m[b][s][tid] = s_m[tid]; g_l[b][s][tid] = s_l[tid]; }
            {
                int c0 = tid, c1 = tid + 256;
                #pragma unroll
                for (int k = 0; k < NH / 2; k++) {
                    float2 a = funpack2(oc0[k]);
                    g_op[b][s][2 * k][c0]     = a.x;
                    g_op[b][s][2 * k + 1][c0] = a.y;
                    float2 c = funpack2(oc1[k]);
                    g_op[b][s][2 * k][c1]     = c.x;
                    g_op[b][s][2 * k + 1][c1] = c.y;
                }
            }
            __syncthreads();
        }
    }
    gsync(6, nb);

    // ===== P6: combine + output projection (float4 reduce) =====
    {
        float* s_olat = (float*)sm_raw;
        float* s_w    = (float*)(sm_raw + 2048);
        float* s_invl = (float*)(sm_raw + 2112);
        for (int u = bx; u < NH * BS; u += nb) {
            int h = u & 15, b = u >> 4;
            if (tid == 0) {
                float M = -1e30f;
                for (int s = 0; s < NSPLIT; s++) M = fmaxf(M, g_m[b][s][h]);
                float L = 0.f;
                for (int s = 0; s < NSPLIT; s++) {
                    float w = __expf(g_m[b][s][h] - M);
                    s_w[s] = w;
                    L += g_l[b][s][h] * w;
                }
                *s_invl = 1.f / L;
            }
            __syncthreads();
            if (tid < 128) {
                int c4 = tid;  // float4 index, 128 x 4 = 512
                float4 a = make_float4(0.f, 0.f, 0.f, 0.f);
                #pragma unroll
                for (int s = 0; s < NSPLIT; s++) {
                    float4 v = ((const float4*)&g_op[b][s][h][0])[c4];
                    float w = s_w[s];
                    a.x += v.x * w; a.y += v.y * w; a.z += v.z * w; a.w += v.w * w;
                }
                float il = *s_invl;
                a.x *= il; a.y *= il; a.z *= il; a.w *= il;
                ((float4*)s_olat)[c4] = a;
            }
            __syncthreads();
            if (tid < DN) {
                int d = tid;
                const float* wk = w_uk + ((size_t)(h * DN + d)) * KVL;
                float a = 0.f;
                #pragma unroll 8
                for (int c = 0; c < KVL; c += 4) {
                    float4 o4 = *(const float4*)&s_olat[c];
                    float4 w4 = *(const float4*)&wk[c];
                    a += o4.x * w4.x + o4.y * w4.y + o4.z * w4.z + o4.w * w4.w;
                }
                out[b * (NH * DN) + h * DN + d] = a;
            }
            __syncthreads();
        }
    }

    // reset sync state for next graph replay
    __syncthreads();
    if (tid == 0) {
        __threadfence();
        unsigned a = atomicAdd(&g_ack, 1u) + 1;
        if (a == (unsigned)nb) {
            #pragma unroll
            for (int i = 0; i < 8; i++) g_barcnt[i] = 0;
            g_ack = 0;
            __threadfence();
        }
    }
}

// ---------------- launch ----------------
extern "C" void kernel_launch(void* const* d_in, const int* in_sizes, int n_in,
                              void* d_out, int out_size) {
    const float* x            = (const float*)d_in[0];
    const float* w_dq         = (const float*)d_in[1];
    const float* w_uq_qr      = (const float*)d_in[2];
    const float* w_uk         = (const float*)d_in[3];
    const float* w_dkv_kr     = (const float*)d_in[4];
    const float* gamma_cq     = (const float*)d_in[5];
    const float* gamma_ckv    = (const float*)d_in[6];
    const float* sinp         = (const float*)d_in[7];
    const float* cosp         = (const float*)d_in[8];
    const int*   cache_index  = (const int*)d_in[9];
    const float* kv_cache     = (const float*)d_in[10];
    const float* kr_cache     = (const float*)d_in[11];
    const int*   block_table  = (const int*)d_in[12];
    const int*   act_seqs     = (const int*)d_in[13];
    const float* w_idx_qb     = (const float*)d_in[14];
    const float* w_idx_k      = (const float*)d_in[15];
    const float* w_idx_proj   = (const float*)d_in[16];
    const float* in_gamma_k   = (const float*)d_in[17];
    const float* in_beta_k    = (const float*)d_in[18];
    const float* index_k_cache= (const float*)d_in[19];
    float* out = (float*)d_out;

    cudaFuncSetAttribute(k_mega, cudaFuncAttributeMaxDynamicSharedMemorySize, SMSZ);

    int sms = 148, bpm = 0;
    cudaDeviceGetAttribute(&sms, cudaDevAttrMultiProcessorCount, 0);
    cudaOccupancyMaxActiveBlocksPerMultiprocessor(&bpm, k_mega, 256, SMSZ);
    if (bpm < 1) bpm = 1;
    int nb = bpm * sms;
    if (nb > NBMAX) nb = NBMAX;

    k_mega<<<nb, 256, SMSZ>>>(x, w_dq, w_uq_qr, w_uk, w_dkv_kr, gamma_cq, gamma_ckv,
                              sinp, cosp, cache_index, kv_cache, kr_cache, block_table,
                              act_seqs, w_idx_qb, w_idx_k, w_idx_proj, in_gamma_k,
                              in_beta_k, index_k_cache, out, nb);
}

// round 16
// speedup vs baseline: 1.0174x; 1.0174x over previous
#include <cuda_runtime.h>
#include <cuda_bf16.h>
#include <math.h>

#define BS 16
#define HDIM 2048
#define QL 768
#define KVL 512
#define DR 64
#define DN 128
#define NH 16
#define NIH 8
#define IDXD 128
#define BLKSZ 128
#define BPS 32
#define MAXKV 4096
#define TOPK 1024
#define NSPLIT 16
#define SPLITROWS 64

#define NZ1 32          /* stage1 K-slices of 64 */
#define NZ2 12          /* stage2 K-slices of 64 */
#define T1DIM 1472
#define T2DIM 4104

#define ATT_SCALE 0.07216878364870323f
#define IDX_SCALE 0.08838834764831845f

#define NBMAX 448
#define SMSZ 57344

typedef unsigned long long ull;

__device__ __forceinline__ ull ffma2(ull a, ull b, ull c) {
    ull d; asm("fma.rn.f32x2 %0, %1, %2, %3;" : "=l"(d) : "l"(a), "l"(b), "l"(c)); return d;
}
__device__ __forceinline__ ull fmul2(ull a, ull b) {
    ull d; asm("mul.rn.f32x2 %0, %1, %2;" : "=l"(d) : "l"(a), "l"(b)); return d;
}
__device__ __forceinline__ ull fpack2(float lo, float hi) {
    ull d; asm("mov.b64 %0, {%1, %2};" : "=l"(d) : "f"(lo), "f"(hi)); return d;
}
__device__ __forceinline__ float2 funpack2(ull v) {
    float lo, hi; asm("mov.b64 {%0, %1}, %2;" : "=f"(lo), "=f"(hi) : "l"(v)); return make_float2(lo, hi);
}

// ---------------- scratch ----------------
__device__ float g_t1p[NZ1][BS][T1DIM];
__device__ float g_t2p[NZ2][BS][T2DIM];
__device__ float g_cq[BS][QL];
__device__ float g_ckv[BS][KVL];
__device__ float g_kr[BS][DR];
__device__ float g_ki[BS][IDXD];
__device__ float g_qpe[BS][NH][DR];
__device__ float g_qlat[BS][NH][KVL];
__device__ float g_isc[BS][MAXKV];
__device__ int   g_sel[BS][TOPK];
__device__ float g_selval[BS][TOPK];
__device__ float g_m[BS][NSPLIT][NH];
__device__ float g_l[BS][NSPLIT][NH];
__device__ float g_op[BS][NSPLIT][NH][KVL];

__device__ unsigned g_barcnt[8];
__device__ unsigned g_ack;

__device__ __forceinline__ void gsync(int id, int nb) {
    __syncthreads();
    if (threadIdx.x == 0) {
        __threadfence();
        atomicAdd(&g_barcnt[id], 1u);
        while (*(volatile unsigned*)&g_barcnt[id] < (unsigned)nb) { __nanosleep(64); }
    }
    __syncthreads();
}

__device__ __forceinline__ float blockSum256(float v, float* buf) {
    int tid = threadIdx.x;
    buf[tid] = v;
    __syncthreads();
    for (int s = 128; s > 0; s >>= 1) {
        if (tid < s) buf[tid] += buf[tid + s];
        __syncthreads();
    }
    float r = buf[0];
    __syncthreads();
    return r;
}

// reduce stage2 partials on the fly
__device__ __forceinline__ float t2sum(int b, int col) {
    float a = 0.f;
    #pragma unroll
    for (int z = 0; z < NZ2; z++) a += g_t2p[z][b][col];
    return a;
}

__global__ void __launch_bounds__(256, 3)
k_mega(const float* __restrict__ x, const float* __restrict__ w_dq,
       const float* __restrict__ w_uq_qr, const float* __restrict__ w_uk,
       const float* __restrict__ w_dkv, const float* __restrict__ gamma_cq,
       const float* __restrict__ gamma_ckv, const float* __restrict__ sinp,
       const float* __restrict__ cosp, const int* __restrict__ cidx,
       const float* __restrict__ kvc, const float* __restrict__ krc,
       const int* __restrict__ bt, const int* __restrict__ act_seqs,
       const float* __restrict__ w_idx_qb, const float* __restrict__ w_idxk,
       const float* __restrict__ w_idx_proj, const float* __restrict__ in_g,
       const float* __restrict__ in_b, const float* __restrict__ ikc,
       float* __restrict__ out, int nb)
{
    extern __shared__ __align__(16) char sm_raw[];
    int tid = threadIdx.x;
    int bx = blockIdx.x;

    // ===== P0: stage1 partials, 8 batches/unit, transposed smem [k][b], FFMA2 =====
    {
        float* s_x = (float*)sm_raw;   // [64][8]
        for (int u = bx; u < 6 * 2 * NZ1; u += nb) {
            int cx = u % 6, bg = (u / 6) & 1, z = u / 12;
            int i0 = z * 64, b0 = bg * 8;
            for (int idx = tid; idx < 512; idx += 256) {
                int i = idx >> 3, b = idx & 7;
                s_x[idx] = x[(b0 + b) * HDIM + i0 + i];
            }
            __syncthreads();
            int col = cx * 256 + tid;
            if (col < T1DIM) {
                const float* W; int stride, c;
                if (col < QL)                 { W = w_dq;   stride = QL;       c = col; }
                else if (col < QL + KVL + DR) { W = w_dkv;  stride = KVL + DR; c = col - QL; }
                else                          { W = w_idxk; stride = IDXD;     c = col - (QL + KVL + DR); }
                const float* wp = W + (size_t)i0 * stride + c;
                ull acc2[4];
                #pragma unroll
                for (int b = 0; b < 4; b++) acc2[b] = 0ull;
                #pragma unroll 8
                for (int i = 0; i < 64; i++) {
                    float w = wp[(size_t)i * stride];
                    ull ww = fpack2(w, w);
                    ulonglong2 xa = *(const ulonglong2*)&s_x[i * 8 + 0];
                    ulonglong2 xb = *(const ulonglong2*)&s_x[i * 8 + 4];
                    acc2[0] = ffma2(xa.x, ww, acc2[0]);
                    acc2[1] = ffma2(xa.y, ww, acc2[1]);
                    acc2[2] = ffma2(xb.x, ww, acc2[2]);
                    acc2[3] = ffma2(xb.y, ww, acc2[3]);
                }
                #pragma unroll
                for (int b = 0; b < 4; b++) {
                    float2 t = funpack2(acc2[b]);
                    g_t1p[z][b0 + 2 * b][col]     = t.x;
                    g_t1p[z][b0 + 2 * b + 1][col] = t.y;
                }
            }
            __syncthreads();
        }
    }
    gsync(0, nb);

    // ===== P1: norms + rope(kr) =====
    {
        float* s_t  = (float*)sm_raw;
        float* sred = (float*)(sm_raw + T1DIM * 4 + 64);
        for (int u = bx; u < BS; u += nb) {
            int b = u;
            for (int i = tid; i < T1DIM; i += 256) {
                float a = 0.f;
                #pragma unroll
                for (int z = 0; z < NZ1; z++) a += g_t1p[z][b][i];
                s_t[i] = a;
            }
            __syncthreads();
            float ss = 0.f;
            for (int i = tid; i < QL; i += 256) ss += s_t[i] * s_t[i];
            ss = blockSum256(ss, sred);
            float r = rsqrtf(ss / (float)QL + 1e-6f);
            for (int i = tid; i < QL; i += 256) g_cq[b][i] = s_t[i] * r * gamma_cq[i];
            float s2 = 0.f;
            for (int i = tid; i < KVL; i += 256) { float v = s_t[QL + i]; s2 += v * v; }
            s2 = blockSum256(s2, sred);
            float r2 = rsqrtf(s2 / (float)KVL + 1e-6f);
            for (int i = tid; i < KVL; i += 256) g_ckv[b][i] = s_t[QL + i] * r2 * gamma_ckv[i];
            if (tid < DR) {
                int d = tid;
                float v = s_t[QL + KVL + d];
                float rot = (d < 32) ? -s_t[QL + KVL + d + 32] : s_t[QL + KVL + d - 32];
                g_kr[b][d] = v * cosp[b * DR + d] + rot * sinp[b * DR + d];
            }
            float sm = 0.f;
            for (int i = tid; i < IDXD; i += 256) sm += s_t[QL + KVL + DR + i];
            sm = blockSum256(sm, sred);
            float mean = sm / (float)IDXD;
            float sv = 0.f;
            for (int i = tid; i < IDXD; i += 256) { float c = s_t[QL + KVL + DR + i] - mean; sv += c * c; }
            sv = blockSum256(sv, sred);
            float rv = rsqrtf(sv / (float)IDXD + 1e-6f);
            for (int i = tid; i < IDXD; i += 256) {
                float c = s_t[QL + KVL + DR + i] - mean;
                g_ki[b][i] = c * rv * in_g[i] + in_b[i];
            }
            __syncthreads();
        }
    }
    gsync(1, nb);

    // ===== P2: stage2 partials, 8 batches/unit, transposed smem, FFMA2 =====
    {
        float* s_cq = (float*)sm_raw;   // [64][8]
        for (int u = bx; u < 17 * 2 * NZ2; u += nb) {
            int cx = u % 17, bg = (u / 17) & 1, z = u / 34;
            int i0 = z * 64, b0 = bg * 8;
            for (int idx = tid; idx < 512; idx += 256) {
                int i = idx >> 3, b = idx & 7;
                s_cq[idx] = g_cq[b0 + b][i0 + i];
            }
            __syncthreads();
            int col = cx * 256 + tid;
            if (col < T2DIM) {
                const float* W; int stride, c;
                if (col < 3072)      { W = w_uq_qr;    stride = 3072; c = col; }
                else if (col < 4096) { W = w_idx_qb;   stride = 1024; c = col - 3072; }
                else                 { W = w_idx_proj; stride = 8;    c = col - 4096; }
                const float* wp = W + (size_t)i0 * stride + c;
                ull acc2[4];
                #pragma unroll
                for (int b = 0; b < 4; b++) acc2[b] = 0ull;
                #pragma unroll 8
                for (int i = 0; i < 64; i++) {
                    float w = wp[(size_t)i * stride];
                    ull ww = fpack2(w, w);
                    ulonglong2 xa = *(const ulonglong2*)&s_cq[i * 8 + 0];
                    ulonglong2 xb = *(const ulonglong2*)&s_cq[i * 8 + 4];
                    acc2[0] = ffma2(xa.x, ww, acc2[0]);
                    acc2[1] = ffma2(xa.y, ww, acc2[1]);
                    acc2[2] = ffma2(xb.x, ww, acc2[2]);
                    acc2[3] = ffma2(xb.y, ww, acc2[3]);
                }
                #pragma unroll
                for (int b = 0; b < 4; b++) {
                    float2 t = funpack2(acc2[b]);
                    g_t2p[z][b0 + 2 * b][col]     = t.x;
                    g_t2p[z][b0 + 2 * b + 1][col] = t.y;
                }
            }
            __syncthreads();
        }
    }
    gsync(2, nb);

    // ===== P3: iscore (512 units) + qprep (64 units); both reduce t2p on the fly =====
    {
        for (int u = bx; u < 512 + 64; u += nb) {
            if (u < 512) {
                float* s_qi = (float*)sm_raw;
                float* s_hw = (float*)(sm_raw + 4096);
                int chunk = u & 31, b = u >> 5;
                for (int i = tid; i < NIH * IDXD; i += 256) s_qi[i] = t2sum(b, 3072 + i);
                if (tid < NIH) s_hw[tid] = t2sum(b, 4096 + tid);
                __syncthreads();
                int warp = tid >> 5, lane = tid & 31;
                int act = act_seqs[b];
                int ci = cidx[b];
                for (int r = warp; r < 128; r += 8) {
                    int n = chunk * 128 + r;
                    if (n >= act) { if (lane == 0) g_isc[b][n] = -1e9f; continue; }
                    int blk = bt[b * BPS + (n >> 7)];
                    long flat = (long)blk * BLKSZ + (n & 127);
                    const float* kr = (flat == (long)ci) ? g_ki[b] : ikc + flat * IDXD;
                    float4 kv = *(const float4*)(kr + lane * 4);
                    float acc[NIH];
                    #pragma unroll
                    for (int h = 0; h < NIH; h++) {
                        float4 q = *(const float4*)&s_qi[h * IDXD + lane * 4];
                        acc[h] = kv.x * q.x + kv.y * q.y + kv.z * q.z + kv.w * q.w;
                    }
                    #pragma unroll
                    for (int off = 16; off; off >>= 1) {
                        #pragma unroll
                        for (int h = 0; h < NIH; h++)
                            acc[h] += __shfl_xor_sync(0xffffffffu, acc[h], off);
                    }
                    if (lane == 0) {
                        float s = 0.f;
                        #pragma unroll
                        for (int h = 0; h < NIH; h++) s += s_hw[h] * fmaxf(acc[h], 0.f);
                        g_isc[b][n] = s * IDX_SCALE;
                    }
                }
                __syncthreads();
            } else {
                int u2 = u - 512;
                int h = u2 & 15, r = u2 >> 4;
                int cc = r & 1, bg = r >> 1;
                int b0 = bg * 8;
                float* s_qn = (float*)sm_raw;  // [128][8] transposed
                for (int idx = tid; idx < 1024; idx += 256) {
                    int d = idx >> 3, bb = idx & 7;
                    s_qn[idx] = t2sum(b0 + bb, h * 192 + d);
                }
                if (cc == 0) {
                    for (int idx = tid; idx < 512; idx += 256) {
                        int bb = idx >> 6, d = idx & 63;
                        int b = b0 + bb;
                        float v = t2sum(b, h * 192 + DN + d);
                        float rot = (d < 32) ? -t2sum(b, h * 192 + DN + d + 32)
                                             :  t2sum(b, h * 192 + DN + d - 32);
                        g_qpe[b][h][d] = v * cosp[b * DR + d] + rot * sinp[b * DR + d];
                    }
                }
                __syncthreads();
                int c = cc * 256 + tid;
                const float* wk = w_uk + (size_t)h * DN * KVL + c;
                ull acc2[4];
                #pragma unroll
                for (int b = 0; b < 4; b++) acc2[b] = 0ull;
                #pragma unroll 8
                for (int d = 0; d < DN; d++) {
                    float w = wk[(size_t)d * KVL];
                    ull ww = fpack2(w, w);
                    ulonglong2 xa = *(const ulonglong2*)&s_qn[d * 8 + 0];
                    ulonglong2 xb = *(const ulonglong2*)&s_qn[d * 8 + 4];
                    acc2[0] = ffma2(xa.x, ww, acc2[0]);
                    acc2[1] = ffma2(xa.y, ww, acc2[1]);
                    acc2[2] = ffma2(xb.x, ww, acc2[2]);
                    acc2[3] = ffma2(xb.y, ww, acc2[3]);
                }
                #pragma unroll
                for (int b = 0; b < 4; b++) {
                    float2 t = funpack2(acc2[b]);
                    g_qlat[b0 + 2 * b][h][c]     = t.x;
                    g_qlat[b0 + 2 * b + 1][h][c] = t.y;
                }
                __syncthreads();
            }
        }
    }
    gsync(3, nb);

    // ===== P4: topk (16 units) =====
    {
        for (int u = bx; u < 16; u += nb) {
            unsigned* s_key  = (unsigned*)sm_raw;
            unsigned* s_hist = (unsigned*)(sm_raw + 16384);
            unsigned* s_scan = (unsigned*)(sm_raw + 17408);
            unsigned* s_bm   = (unsigned*)(sm_raw + 18432);
            unsigned* s_cnt  = (unsigned*)(sm_raw + 18944);
            unsigned* s_pref = (unsigned*)(sm_raw + 18948);
            int*      s_rem  = (int*)(sm_raw + 18952);
            int*      s_Bw   = (int*)(sm_raw + 18956);
            int*      s_need = (int*)(sm_raw + 18960);
            int b = u;
            int act = act_seqs[b];
            for (int i = tid; i < MAXKV; i += 256) {
                float v = (i < act) ? g_isc[b][i] : -1e9f;
                unsigned uu = __float_as_uint(v);
                uu = (uu & 0x80000000u) ? ~uu : (uu | 0x80000000u);
                s_key[i] = uu;
            }
            if (tid == 0) { *s_cnt = 0; *s_rem = TOPK; *s_pref = 0; }
            __syncthreads();
            for (int level = 0; level < 4; level++) {
                int shift = 24 - level * 8;
                s_hist[tid] = 0;
                __syncthreads();
                unsigned pref = *s_pref;
                for (int i = tid; i < MAXKV; i += 256) {
                    unsigned uu = s_key[i];
                    if (level == 0 || (uu >> (shift + 8)) == pref)
                        atomicAdd(&s_hist[(uu >> shift) & 255u], 1u);
                }
                __syncthreads();
                s_scan[tid] = s_hist[tid];
                __syncthreads();
                #pragma unroll
                for (int off = 1; off < 256; off <<= 1) {
                    unsigned t = (tid + off < 256) ? s_scan[tid + off] : 0u;
                    __syncthreads();
                    s_scan[tid] += t;
                    __syncthreads();
                }
                int rem = *s_rem;
                unsigned cumGT = s_scan[tid] - s_hist[tid];
                if ((int)cumGT < rem && (int)s_scan[tid] >= rem) {
                    *s_pref = (pref << 8) | (unsigned)tid;
                    *s_rem = rem - (int)cumGT;
                }
                __syncthreads();
            }
            unsigned K = *s_pref;
            for (int i = tid; i < MAXKV; i += 256) {
                if (s_key[i] > K) {
                    unsigned pos = atomicAdd(s_cnt, 1u);
                    g_sel[b][pos] = i;
                    g_selval[b][pos] = (i < act) ? g_isc[b][i] : -1e9f;
                }
            }
            for (int w = tid; w < MAXKV / 32; w += 256) s_bm[w] = 0;
            __syncthreads();
            for (int i = tid; i < MAXKV; i += 256)
                if (s_key[i] == K) atomicOr(&s_bm[i >> 5], 1u << (i & 31));
            __syncthreads();
            if (tid == 0) {
                int need = *s_rem;
                int w = 0;
                for (; w < MAXKV / 32; w++) {
                    int pc = __popc(s_bm[w]);
                    if (pc >= need) break;
                    need -= pc;
                }
                *s_Bw = w; *s_need = need;
            }
            __syncthreads();
            int Bw = *s_Bw, need = *s_need;
            for (int i = tid; i < MAXKV; i += 256) {
                if (s_key[i] == K) {
                    int w = i >> 5, bit = i & 31;
                    bool take = (w < Bw) ||
                                (w == Bw && (int)__popc(s_bm[w] & ((1u << bit) - 1u)) < need);
                    if (take) {
                        unsigned pos = atomicAdd(s_cnt, 1u);
                        g_sel[b][pos] = i;
                        g_selval[b][pos] = (i < act) ? g_isc[b][i] : -1e9f;
                    }
                }
            }
            __syncthreads();
        }
    }
    gsync(4, nb);

    // ===== P5: attention partials — online softmax, smem-staged KV, FFMA2 (256 units) =====
    {
        float* s_qlat = (float*)sm_raw;                       // 32768 B
        float* s_qpe  = (float*)(sm_raw + 32768);             //  4096 B
        float* s_kv   = (float*)(sm_raw + 36864);             // 16384 B (8 rows x 512)
        float* s_kr   = (float*)(sm_raw + 53248);             //  2048 B (8 rows x 64)
        float* s_sc   = (float*)(sm_raw + 55296);             //   512 B (8 x 16)
        float* s_m    = (float*)(sm_raw + 55808);
        float* s_l    = (float*)(sm_raw + 55872);
        float* s_fac  = (float*)(sm_raw + 55936);
        const float** s_ckvp = (const float**)(sm_raw + 56064);
        const float** s_krp  = (const float**)(sm_raw + 56576);
        int* s_vld = (int*)(sm_raw + 57088);
        for (int u = bx; u < NSPLIT * BS; u += nb) {
            int s = u & 15, b = u >> 4;
            const float4* qlb = (const float4*)&g_qlat[b][0][0];
            for (int i = tid; i < NH * KVL / 4; i += 256) ((float4*)s_qlat)[i] = qlb[i];
            const float4* qpb = (const float4*)&g_qpe[b][0][0];
            for (int i = tid; i < NH * DR / 4; i += 256) ((float4*)s_qpe)[i] = qpb[i];
            if (tid < SPLITROWS) {
                int j = tid;
                int n = g_sel[b][s * SPLITROWS + j];
                float v = g_selval[b][s * SPLITROWS + j];
                bool valid = v > -1e8f;
                const float* cp; const float* kp;
                if (!valid) { cp = g_ckv[b]; kp = g_kr[b]; }
                else {
                    int blk = bt[b * BPS + (n >> 7)];
                    long flat = (long)blk * BLKSZ + (n & 127);
                    if (flat == (long)cidx[b]) { cp = g_ckv[b]; kp = g_kr[b]; }
                    else { cp = kvc + flat * KVL; kp = krc + flat * DR; }
                }
                s_ckvp[j] = cp; s_krp[j] = kp; s_vld[j] = valid ? 1 : 0;
            }
            if (tid < NH) { s_m[tid] = -1e30f; s_l[tid] = 0.f; }
            ull oc0[NH / 2], oc1[NH / 2];
            #pragma unroll
            for (int k = 0; k < NH / 2; k++) { oc0[k] = 0ull; oc1[k] = 0ull; }
            __syncthreads();
            int warp = tid >> 5, lane = tid & 31;
            for (int g = 0; g < SPLITROWS / 8; g++) {
                #pragma unroll
                for (int k = 0; k < 4; k++) {
                    int f = tid + 256 * k;
                    int r = f >> 7, pos = f & 127;
                    ((float4*)&s_kv[r * 512])[pos] = ((const float4*)s_ckvp[g * 8 + r])[pos];
                }
                if (tid < 128) {
                    int r = tid >> 4, pos = tid & 15;
                    ((float4*)&s_kr[r * 64])[pos] = ((const float4*)s_krp[g * 8 + r])[pos];
                }
                __syncthreads();
                {
                    int j = warp;
                    ull acc2[NH];
                    #pragma unroll
                    for (int h = 0; h < NH; h++) acc2[h] = 0ull;
                    #pragma unroll
                    for (int q = 0; q < 4; q++) {
                        ulonglong2 v = *(const ulonglong2*)&s_kv[j * 512 + 4 * (lane + 32 * q)];
                        #pragma unroll
                        for (int h = 0; h < NH; h++) {
                            ulonglong2 ql = *(const ulonglong2*)&s_qlat[h * KVL + 4 * (lane + 32 * q)];
                            acc2[h] = ffma2(v.x, ql.x, acc2[h]);
                            acc2[h] = ffma2(v.y, ql.y, acc2[h]);
                        }
                    }
                    ull kvr = *(const ull*)&s_kr[j * 64 + 2 * lane];
                    float acc[NH];
                    #pragma unroll
                    for (int h = 0; h < NH; h++) {
                        ull qp = *(const ull*)&s_qpe[h * DR + 2 * lane];
                        acc2[h] = ffma2(kvr, qp, acc2[h]);
                        float2 t = funpack2(acc2[h]);
                        acc[h] = t.x + t.y;
                    }
                    #pragma unroll
                    for (int off = 16; off; off >>= 1) {
                        #pragma unroll
                        for (int h = 0; h < NH; h++)
                            acc[h] += __shfl_xor_sync(0xffffffffu, acc[h], off);
                    }
                    if (lane == 0) {
                        bool valid = s_vld[g * 8 + j] != 0;
                        #pragma unroll
                        for (int h = 0; h < NH; h++)
                            s_sc[j * NH + h] = valid ? acc[h] * ATT_SCALE : -1e9f;
                    }
                }
                __syncthreads();
                #pragma unroll
                for (int hh = warp; hh < NH; hh += 8) {
                    float sc = (lane < 8) ? s_sc[lane * NH + hh] : -3.0e38f;
                    float gm = sc;
                    #pragma unroll
                    for (int off = 4; off; off >>= 1) gm = fmaxf(gm, __shfl_xor_sync(0xffffffffu, gm, off));
                    float oldm = s_m[hh];
                    float newm = fmaxf(oldm, gm);
                    float p = (lane < 8) ? __expf(sc - newm) : 0.f;
                    float sl = p;
                    #pragma unroll
                    for (int off = 4; off; off >>= 1) sl += __shfl_xor_sync(0xffffffffu, sl, off);
                    if (lane < 8) s_sc[lane * NH + hh] = p;
                    if (lane == 0) {
                        float fac = __expf(oldm - newm);
                        s_m[hh] = newm;
                        s_l[hh] = s_l[hh] * fac + sl;
                        s_fac[hh] = fac;
                    }
                }
                __syncthreads();
                {
                    const ull* facp = (const ull*)s_fac;
                    #pragma unroll
                    for (int k = 0; k < NH / 2; k++) {
                        ull f = facp[k];
                        oc0[k] = fmul2(oc0[k], f);
                        oc1[k] = fmul2(oc1[k], f);
                    }
                    int c0 = tid, c1 = tid + 256;
                    #pragma unroll
                    for (int j = 0; j < 8; j++) {
                        float va = s_kv[j * 512 + c0];
                        float vb = s_kv[j * 512 + c1];
                        ull vva = fpack2(va, va);
                        ull vvb = fpack2(vb, vb);
                        const ull* pp = (const ull*)&s_sc[j * NH];
                        #pragma unroll
                        for (int k = 0; k < NH / 2; k++) {
                            ull p = pp[k];
                            oc0[k] = ffma2(p, vva, oc0[k]);
                            oc1[k] = ffma2(p, vvb, oc1[k]);
                        }
                    }
                }
                __syncthreads();
            }
            if (tid < NH) { g_m[b][s][tid] = s_m[tid]; g_l[b][s][tid] = s_l[tid]; }
            {
                int c0 = tid, c1 = tid + 256;
                #pragma unroll
                for (int k = 0; k < NH / 2; k++) {
                    float2 a = funpack2(oc0[k]);
                    g_op[b][s][2 * k][c0]     = a.x;
                    g_op[b][s][2 * k + 1][c0] = a.y;
                    float2 c = funpack2(oc1[k]);
                    g_op[b][s][2 * k][c1]     = c.x;
                    g_op[b][s][2 * k + 1][c1] = c.y;
                }
            }
            __syncthreads();
        }
    }
    gsync(5, nb);

    // ===== P6: combine + output projection (float4 reduce) =====
    {
        float* s_olat = (float*)sm_raw;
        float* s_w    = (float*)(sm_raw + 2048);
        float* s_invl = (float*)(sm_raw + 2112);
        for (int u = bx; u < NH * BS; u += nb) {
            int h = u & 15, b = u >> 4;
            if (tid == 0) {
                float M = -1e30f;
                for (int s = 0; s < NSPLIT; s++) M = fmaxf(M, g_m[b][s][h]);
                float L = 0.f;
                for (int s = 0; s < NSPLIT; s++) {
                    float w = __expf(g_m[b][s][h] - M);
                    s_w[s] = w;
                    L += g_l[b][s][h] * w;
                }
                *s_invl = 1.f / L;
            }
            __syncthreads();
            if (tid < 128) {
                int c4 = tid;
                float4 a = make_float4(0.f, 0.f, 0.f, 0.f);
                #pragma unroll
                for (int s = 0; s < NSPLIT; s++) {
                    float4 v = ((const float4*)&g_op[b][s][h][0])[c4];
                    float w = s_w[s];
                    a.x += v.x * w; a.y += v.y * w; a.z += v.z * w; a.w += v.w * w;
                }
                float il = *s_invl;
                a.x *= il; a.y *= il; a.z *= il; a.w *= il;
                ((float4*)s_olat)[c4] = a;
            }
            __syncthreads();
            if (tid < DN) {
                int d = tid;
                const float* wk = w_uk + ((size_t)(h * DN + d)) * KVL;
                float a = 0.f;
                #pragma unroll 8
                for (int c = 0; c < KVL; c += 4) {
                    float4 o4 = *(const float4*)&s_olat[c];
                    float4 w4 = *(const float4*)&wk[c];
                    a += o4.x * w4.x + o4.y * w4.y + o4.z * w4.z + o4.w * w4.w;
                }
                out[b * (NH * DN) + h * DN + d] = a;
            }
            __syncthreads();
        }
    }

    // reset sync state for next graph replay
    __syncthreads();
    if (tid == 0) {
        __threadfence();
        unsigned a = atomicAdd(&g_ack, 1u) + 1;
        if (a == (unsigned)nb) {
            #pragma unroll
            for (int i = 0; i < 8; i++) g_barcnt[i] = 0;
            g_ack = 0;
            __threadfence();
        }
    }
}

// ---------------- launch ----------------
extern "C" void kernel_launch(void* const* d_in, const int* in_sizes, int n_in,
                              void* d_out, int out_size) {
    const float* x            = (const float*)d_in[0];
    const float* w_dq         = (const float*)d_in[1];
    const float* w_uq_qr      = (const float*)d_in[2];
    const float* w_uk         = (const float*)d_in[3];
    const float* w_dkv_kr     = (const float*)d_in[4];
    const float* gamma_cq     = (const float*)d_in[5];
    const float* gamma_ckv    = (const float*)d_in[6];
    const float* sinp         = (const float*)d_in[7];
    const float* cosp         = (const float*)d_in[8];
    const int*   cache_index  = (const int*)d_in[9];
    const float* kv_cache     = (const float*)d_in[10];
    const float* kr_cache     = (const float*)d_in[11];
    const int*   block_table  = (const int*)d_in[12];
    const int*   act_seqs     = (const int*)d_in[13];
    const float* w_idx_qb     = (const float*)d_in[14];
    const float* w_idx_k      = (const float*)d_in[15];
    const float* w_idx_proj   = (const float*)d_in[16];
    const float* in_gamma_k   = (const float*)d_in[17];
    const float* in_beta_k    = (const float*)d_in[18];
    const float* index_k_cache= (const float*)d_in[19];
    float* out = (float*)d_out;

    cudaFuncSetAttribute(k_mega, cudaFuncAttributeMaxDynamicSharedMemorySize, SMSZ);

    int sms = 148, bpm = 0;
    cudaDeviceGetAttribute(&sms, cudaDevAttrMultiProcessorCount, 0);
    cudaOccupancyMaxActiveBlocksPerMultiprocessor(&bpm, k_mega, 256, SMSZ);
    if (bpm < 1) bpm = 1;
    int nb = bpm * sms;
    if (nb > NBMAX) nb = NBMAX;

    k_mega<<<nb, 256, SMSZ>>>(x, w_dq, w_uq_qr, w_uk, w_dkv_kr, gamma_cq, gamma_ckv,
                              sinp, cosp, cache_index, kv_cache, kr_cache, block_table,
                              act_seqs, w_idx_qb, w_idx_k, w_idx_proj, in_gamma_k,
                              in_beta_k, index_k_cache, out, nb);
}

// round 17
// speedup vs baseline: 1.0462x; 1.0283x over previous
#include <cuda_runtime.h>
#include <cuda_bf16.h>
#include <math.h>

#define BS 16
#define HDIM 2048
#define QL 768
#define KVL 512
#define DR 64
#define DN 128
#define NH 16
#define NIH 8
#define IDXD 128
#define BLKSZ 128
#define BPS 32
#define MAXKV 4096
#define TOPK 1024
#define NSPLIT 16
#define SPLITROWS 64

#define NZ1 32          /* stage1 K-slices of 64 */
#define NZ2 12          /* stage2 K-slices of 64 */
#define T1DIM 1472
#define T2DIM 4104

#define ATT_SCALE 0.07216878364870323f
#define IDX_SCALE 0.08838834764831845f

#define NBMAX 448
#define SMSZ 57344

typedef unsigned long long ull;

__device__ __forceinline__ ull ffma2(ull a, ull b, ull c) {
    ull d; asm("fma.rn.f32x2 %0, %1, %2, %3;" : "=l"(d) : "l"(a), "l"(b), "l"(c)); return d;
}
__device__ __forceinline__ ull fmul2(ull a, ull b) {
    ull d; asm("mul.rn.f32x2 %0, %1, %2;" : "=l"(d) : "l"(a), "l"(b)); return d;
}
__device__ __forceinline__ ull fpack2(float lo, float hi) {
    ull d; asm("mov.b64 %0, {%1, %2};" : "=l"(d) : "f"(lo), "f"(hi)); return d;
}
__device__ __forceinline__ float2 funpack2(ull v) {
    float lo, hi; asm("mov.b64 {%0, %1}, %2;" : "=f"(lo), "=f"(hi) : "l"(v)); return make_float2(lo, hi);
}

// ---------------- scratch ----------------
__device__ float g_t1p[NZ1][BS][T1DIM];
__device__ float g_t2p[NZ2][BS][T2DIM];
__device__ float g_cq[BS][QL];
__device__ float g_ckv[BS][KVL];
__device__ float g_kr[BS][DR];
__device__ float g_ki[BS][IDXD];
__device__ float g_qpe[BS][NH][DR];
__device__ float g_qlat[BS][NH][KVL];
__device__ float g_isc[BS][MAXKV];
__device__ int   g_sel[BS][TOPK];
__device__ float g_selval[BS][TOPK];
__device__ float g_m[BS][NSPLIT][NH];
__device__ float g_l[BS][NSPLIT][NH];
__device__ float g_op[BS][NSPLIT][NH][KVL];

__device__ unsigned g_barcnt[8];
__device__ unsigned g_ack;

__device__ __forceinline__ void gsync(int id, int nb) {
    __syncthreads();
    if (threadIdx.x == 0) {
        __threadfence();
        atomicAdd(&g_barcnt[id], 1u);
        while (*(volatile unsigned*)&g_barcnt[id] < (unsigned)nb) { __nanosleep(64); }
    }
    __syncthreads();
}

__device__ __forceinline__ float blockSum256(float v, float* buf) {
    int tid = threadIdx.x;
    buf[tid] = v;
    __syncthreads();
    for (int s = 128; s > 0; s >>= 1) {
        if (tid < s) buf[tid] += buf[tid + s];
        __syncthreads();
    }
    float r = buf[0];
    __syncthreads();
    return r;
}

// reduce stage2 partials on the fly
__device__ __forceinline__ float t2sum(int b, int col) {
    float a = 0.f;
    #pragma unroll
    for (int z = 0; z < NZ2; z++) a += g_t2p[z][b][col];
    return a;
}

__global__ void __launch_bounds__(256, 3)
k_mega(const float* __restrict__ x, const float* __restrict__ w_dq,
       const float* __restrict__ w_uq_qr, const float* __restrict__ w_uk,
       const float* __restrict__ w_dkv, const float* __restrict__ gamma_cq,
       const float* __restrict__ gamma_ckv, const float* __restrict__ sinp,
       const float* __restrict__ cosp, const int* __restrict__ cidx,
       const float* __restrict__ kvc, const float* __restrict__ krc,
       const int* __restrict__ bt, const int* __restrict__ act_seqs,
       const float* __restrict__ w_idx_qb, const float* __restrict__ w_idxk,
       const float* __restrict__ w_idx_proj, const float* __restrict__ in_g,
       const float* __restrict__ in_b, const float* __restrict__ ikc,
       float* __restrict__ out, int nb)
{
    extern __shared__ __align__(16) char sm_raw[];
    int tid = threadIdx.x;
    int bx = blockIdx.x;

    // ===== P0: stage1 partials, 8 batches/unit, transposed smem [k][b], FFMA2 =====
    {
        float* s_x = (float*)sm_raw;   // [64][8]
        for (int u = bx; u < 6 * 2 * NZ1; u += nb) {
            int cx = u % 6, bg = (u / 6) & 1, z = u / 12;
            int i0 = z * 64, b0 = bg * 8;
            for (int idx = tid; idx < 512; idx += 256) {
                int i = idx >> 3, b = idx & 7;
                s_x[idx] = x[(b0 + b) * HDIM + i0 + i];
            }
            __syncthreads();
            int col = cx * 256 + tid;
            if (col < T1DIM) {
                const float* W; int stride, c;
                if (col < QL)                 { W = w_dq;   stride = QL;       c = col; }
                else if (col < QL + KVL + DR) { W = w_dkv;  stride = KVL + DR; c = col - QL; }
                else                          { W = w_idxk; stride = IDXD;     c = col - (QL + KVL + DR); }
                const float* wp = W + (size_t)i0 * stride + c;
                ull acc2[4];
                #pragma unroll
                for (int b = 0; b < 4; b++) acc2[b] = 0ull;
                #pragma unroll 8
                for (int i = 0; i < 64; i++) {
                    float w = wp[(size_t)i * stride];
                    ull ww = fpack2(w, w);
                    ulonglong2 xa = *(const ulonglong2*)&s_x[i * 8 + 0];
                    ulonglong2 xb = *(const ulonglong2*)&s_x[i * 8 + 4];
                    acc2[0] = ffma2(xa.x, ww, acc2[0]);
                    acc2[1] = ffma2(xa.y, ww, acc2[1]);
                    acc2[2] = ffma2(xb.x, ww, acc2[2]);
                    acc2[3] = ffma2(xb.y, ww, acc2[3]);
                }
                #pragma unroll
                for (int b = 0; b < 4; b++) {
                    float2 t = funpack2(acc2[b]);
                    g_t1p[z][b0 + 2 * b][col]     = t.x;
                    g_t1p[z][b0 + 2 * b + 1][col] = t.y;
                }
            }
            __syncthreads();
        }
    }
    gsync(0, nb);

    // ===== P1: norms + rope(kr) =====
    {
        float* s_t  = (float*)sm_raw;
        float* sred = (float*)(sm_raw + T1DIM * 4 + 64);
        for (int u = bx; u < BS; u += nb) {
            int b = u;
            for (int i = tid; i < T1DIM; i += 256) {
                float a = 0.f;
                #pragma unroll
                for (int z = 0; z < NZ1; z++) a += g_t1p[z][b][i];
                s_t[i] = a;
            }
            __syncthreads();
            float ss = 0.f;
            for (int i = tid; i < QL; i += 256) ss += s_t[i] * s_t[i];
            ss = blockSum256(ss, sred);
            float r = rsqrtf(ss / (float)QL + 1e-6f);
            for (int i = tid; i < QL; i += 256) g_cq[b][i] = s_t[i] * r * gamma_cq[i];
            float s2 = 0.f;
            for (int i = tid; i < KVL; i += 256) { float v = s_t[QL + i]; s2 += v * v; }
            s2 = blockSum256(s2, sred);
            float r2 = rsqrtf(s2 / (float)KVL + 1e-6f);
            for (int i = tid; i < KVL; i += 256) g_ckv[b][i] = s_t[QL + i] * r2 * gamma_ckv[i];
            if (tid < DR) {
                int d = tid;
                float v = s_t[QL + KVL + d];
                float rot = (d < 32) ? -s_t[QL + KVL + d + 32] : s_t[QL + KVL + d - 32];
                g_kr[b][d] = v * cosp[b * DR + d] + rot * sinp[b * DR + d];
            }
            float sm = 0.f;
            for (int i = tid; i < IDXD; i += 256) sm += s_t[QL + KVL + DR + i];
            sm = blockSum256(sm, sred);
            float mean = sm / (float)IDXD;
            float sv = 0.f;
            for (int i = tid; i < IDXD; i += 256) { float c = s_t[QL + KVL + DR + i] - mean; sv += c * c; }
            sv = blockSum256(sv, sred);
            float rv = rsqrtf(sv / (float)IDXD + 1e-6f);
            for (int i = tid; i < IDXD; i += 256) {
                float c = s_t[QL + KVL + DR + i] - mean;
                g_ki[b][i] = c * rv * in_g[i] + in_b[i];
            }
            __syncthreads();
        }
    }
    gsync(1, nb);

    // ===== P2: stage2 partials, 8 batches/unit, transposed smem, FFMA2 =====
    {
        float* s_cq = (float*)sm_raw;   // [64][8]
        for (int u = bx; u < 17 * 2 * NZ2; u += nb) {
            int cx = u % 17, bg = (u / 17) & 1, z = u / 34;
            int i0 = z * 64, b0 = bg * 8;
            for (int idx = tid; idx < 512; idx += 256) {
                int i = idx >> 3, b = idx & 7;
                s_cq[idx] = g_cq[b0 + b][i0 + i];
            }
            __syncthreads();
            int col = cx * 256 + tid;
            if (col < T2DIM) {
                const float* W; int stride, c;
                if (col < 3072)      { W = w_uq_qr;    stride = 3072; c = col; }
                else if (col < 4096) { W = w_idx_qb;   stride = 1024; c = col - 3072; }
                else                 { W = w_idx_proj; stride = 8;    c = col - 4096; }
                const float* wp = W + (size_t)i0 * stride + c;
                ull acc2[4];
                #pragma unroll
                for (int b = 0; b < 4; b++) acc2[b] = 0ull;
                #pragma unroll 8
                for (int i = 0; i < 64; i++) {
                    float w = wp[(size_t)i * stride];
                    ull ww = fpack2(w, w);
                    ulonglong2 xa = *(const ulonglong2*)&s_cq[i * 8 + 0];
                    ulonglong2 xb = *(const ulonglong2*)&s_cq[i * 8 + 4];
                    acc2[0] = ffma2(xa.x, ww, acc2[0]);
                    acc2[1] = ffma2(xa.y, ww, acc2[1]);
                    acc2[2] = ffma2(xb.x, ww, acc2[2]);
                    acc2[3] = ffma2(xb.y, ww, acc2[3]);
                }
                #pragma unroll
                for (int b = 0; b < 4; b++) {
                    float2 t = funpack2(acc2[b]);
                    g_t2p[z][b0 + 2 * b][col]     = t.x;
                    g_t2p[z][b0 + 2 * b + 1][col] = t.y;
                }
            }
            __syncthreads();
        }
    }
    gsync(2, nb);

    // ===== P3: iscore (512 units, load-pipelined) + qprep (64 units) =====
    {
        for (int u = bx; u < 512 + 64; u += nb) {
            if (u < 512) {
                float* s_qi = (float*)sm_raw;
                float* s_hw = (float*)(sm_raw + 4096);
                int chunk = u & 31, b = u >> 5;
                for (int i = tid; i < NIH * IDXD; i += 256) s_qi[i] = t2sum(b, 3072 + i);
                if (tid < NIH) s_hw[tid] = t2sum(b, 4096 + tid);
                __syncthreads();
                int warp = tid >> 5, lane = tid & 31;
                int act = act_seqs[b];
                int ci = cidx[b];
                int blk = bt[b * BPS + chunk];              // invariant: n>>7 == chunk
                long base = (long)blk * BLKSZ;
                // prefetch first row
                bool vld;
                float4 kv;
                {
                    int n = chunk * 128 + warp;
                    vld = n < act;
                    if (vld) {
                        long flat = base + warp;
                        const float* p = (flat == (long)ci) ? g_ki[b] : ikc + flat * IDXD;
                        kv = *(const float4*)(p + lane * 4);
                    }
                }
                for (int r = warp; r < 128; r += 8) {
                    // prefetch next row before the dependent chain
                    bool vldn = false;
                    float4 kvn;
                    int rn = r + 8;
                    if (rn < 128) {
                        int nn = chunk * 128 + rn;
                        vldn = nn < act;
                        if (vldn) {
                            long flat = base + rn;
                            const float* p = (flat == (long)ci) ? g_ki[b] : ikc + flat * IDXD;
                            kvn = *(const float4*)(p + lane * 4);
                        }
                    }
                    int n = chunk * 128 + r;
                    if (vld) {
                        float acc[NIH];
                        #pragma unroll
                        for (int h = 0; h < NIH; h++) {
                            float4 q = *(const float4*)&s_qi[h * IDXD + lane * 4];
                            acc[h] = kv.x * q.x + kv.y * q.y + kv.z * q.z + kv.w * q.w;
                        }
                        #pragma unroll
                        for (int off = 16; off; off >>= 1) {
                            #pragma unroll
                            for (int h = 0; h < NIH; h++)
                                acc[h] += __shfl_xor_sync(0xffffffffu, acc[h], off);
                        }
                        if (lane == 0) {
                            float s = 0.f;
                            #pragma unroll
                            for (int h = 0; h < NIH; h++) s += s_hw[h] * fmaxf(acc[h], 0.f);
                            g_isc[b][n] = s * IDX_SCALE;
                        }
                    } else {
                        if (lane == 0) g_isc[b][n] = -1e9f;
                    }
                    vld = vldn; kv = kvn;
                }
                __syncthreads();
            } else {
                int u2 = u - 512;
                int h = u2 & 15, r = u2 >> 4;
                int cc = r & 1, bg = r >> 1;
                int b0 = bg * 8;
                float* s_qn = (float*)sm_raw;  // [128][8] transposed
                for (int idx = tid; idx < 1024; idx += 256) {
                    int d = idx >> 3, bb = idx & 7;
                    s_qn[idx] = t2sum(b0 + bb, h * 192 + d);
                }
                if (cc == 0) {
                    for (int idx = tid; idx < 512; idx += 256) {
                        int bb = idx >> 6, d = idx & 63;
                        int b = b0 + bb;
                        float v = t2sum(b, h * 192 + DN + d);
                        float rot = (d < 32) ? -t2sum(b, h * 192 + DN + d + 32)
                                             :  t2sum(b, h * 192 + DN + d - 32);
                        g_qpe[b][h][d] = v * cosp[b * DR + d] + rot * sinp[b * DR + d];
                    }
                }
                __syncthreads();
                int c = cc * 256 + tid;
                const float* wk = w_uk + (size_t)h * DN * KVL + c;
                ull acc2[4];
                #pragma unroll
                for (int b = 0; b < 4; b++) acc2[b] = 0ull;
                #pragma unroll 8
                for (int d = 0; d < DN; d++) {
                    float w = wk[(size_t)d * KVL];
                    ull ww = fpack2(w, w);
                    ulonglong2 xa = *(const ulonglong2*)&s_qn[d * 8 + 0];
                    ulonglong2 xb = *(const ulonglong2*)&s_qn[d * 8 + 4];
                    acc2[0] = ffma2(xa.x, ww, acc2[0]);
                    acc2[1] = ffma2(xa.y, ww, acc2[1]);
                    acc2[2] = ffma2(xb.x, ww, acc2[2]);
                    acc2[3] = ffma2(xb.y, ww, acc2[3]);
                }
                #pragma unroll
                for (int b = 0; b < 4; b++) {
                    float2 t = funpack2(acc2[b]);
                    g_qlat[b0 + 2 * b][h][c]     = t.x;
                    g_qlat[b0 + 2 * b + 1][h][c] = t.y;
                }
                __syncthreads();
            }
        }
    }
    gsync(3, nb);

    // ===== P4: topk (16 units), warp-shuffle suffix scan =====
    {
        for (int u = bx; u < 16; u += nb) {
            unsigned* s_key  = (unsigned*)sm_raw;
            unsigned* s_hist = (unsigned*)(sm_raw + 16384);
            unsigned* s_wt   = (unsigned*)(sm_raw + 17408);   // 8 warp totals
            unsigned* s_bm   = (unsigned*)(sm_raw + 18432);
            unsigned* s_cnt  = (unsigned*)(sm_raw + 18944);
            unsigned* s_pref = (unsigned*)(sm_raw + 18948);
            int*      s_rem  = (int*)(sm_raw + 18952);
            int*      s_Bw   = (int*)(sm_raw + 18956);
            int*      s_need = (int*)(sm_raw + 18960);
            int b = u;
            int act = act_seqs[b];
            for (int i = tid; i < MAXKV; i += 256) {
                float v = (i < act) ? g_isc[b][i] : -1e9f;
                unsigned uu = __float_as_uint(v);
                uu = (uu & 0x80000000u) ? ~uu : (uu | 0x80000000u);
                s_key[i] = uu;
            }
            if (tid == 0) { *s_cnt = 0; *s_rem = TOPK; *s_pref = 0; }
            __syncthreads();
            int lane = tid & 31, wid = tid >> 5;
            for (int level = 0; level < 4; level++) {
                int shift = 24 - level * 8;
                s_hist[tid] = 0;
                __syncthreads();
                unsigned pref = *s_pref;
                for (int i = tid; i < MAXKV; i += 256) {
                    unsigned uu = s_key[i];
                    if (level == 0 || (uu >> (shift + 8)) == pref)
                        atomicAdd(&s_hist[(uu >> shift) & 255u], 1u);
                }
                __syncthreads();
                // warp-shuffle inclusive suffix scan over 256 bins
                unsigned hv = s_hist[tid];
                unsigned v = hv;
                #pragma unroll
                for (int off = 1; off < 32; off <<= 1) {
                    unsigned t = __shfl_down_sync(0xffffffffu, v, off);
                    if (lane < 32 - off) v += t;
                }
                if (lane == 0) s_wt[wid] = v;
                __syncthreads();
                unsigned vtot = v;
                #pragma unroll
                for (int w = 0; w < 8; w++)
                    if (w > wid) vtot += s_wt[w];
                int rem = *s_rem;
                unsigned cumGT = vtot - hv;
                if ((int)cumGT < rem && (int)vtot >= rem) {
                    *s_pref = (pref << 8) | (unsigned)tid;
                    *s_rem = rem - (int)cumGT;
                }
                __syncthreads();
            }
            unsigned K = *s_pref;
            for (int i = tid; i < MAXKV; i += 256) {
                if (s_key[i] > K) {
                    unsigned pos = atomicAdd(s_cnt, 1u);
                    g_sel[b][pos] = i;
                    g_selval[b][pos] = (i < act) ? g_isc[b][i] : -1e9f;
                }
            }
            for (int w = tid; w < MAXKV / 32; w += 256) s_bm[w] = 0;
            __syncthreads();
            for (int i = tid; i < MAXKV; i += 256)
                if (s_key[i] == K) atomicOr(&s_bm[i >> 5], 1u << (i & 31));
            __syncthreads();
            if (tid == 0) {
                int need = *s_rem;
                int w = 0;
                for (; w < MAXKV / 32; w++) {
                    int pc = __popc(s_bm[w]);
                    if (pc >= need) break;
                    need -= pc;
                }
                *s_Bw = w; *s_need = need;
            }
            __syncthreads();
            int Bw = *s_Bw, need = *s_need;
            for (int i = tid; i < MAXKV; i += 256) {
                if (s_key[i] == K) {
                    int w = i >> 5, bit = i & 31;
                    bool take = (w < Bw) ||
                                (w == Bw && (int)__popc(s_bm[w] & ((1u << bit) - 1u)) < need);
                    if (take) {
                        unsigned pos = atomicAdd(s_cnt, 1u);
                        g_sel[b][pos] = i;
                        g_selval[b][pos] = (i < act) ? g_isc[b][i] : -1e9f;
                    }
                }
            }
            __syncthreads();
        }
    }
    gsync(4, nb);

    // ===== P5: attention partials — online softmax, smem-staged KV, FFMA2 (256 units) =====
    {
        float* s_qlat = (float*)sm_raw;                       // 32768 B
        float* s_qpe  = (float*)(sm_raw + 32768);             //  4096 B
        float* s_kv   = (float*)(sm_raw + 36864);             // 16384 B (8 rows x 512)
        float* s_kr   = (float*)(sm_raw + 53248);             //  2048 B (8 rows x 64)
        float* s_sc   = (float*)(sm_raw + 55296);             //   512 B (8 x 16)
        float* s_m    = (float*)(sm_raw + 55808);
        float* s_l    = (float*)(sm_raw + 55872);
        float* s_fac  = (float*)(sm_raw + 55936);
        const float** s_ckvp = (const float**)(sm_raw + 56064);
        const float** s_krp  = (const float**)(sm_raw + 56576);
        int* s_vld = (int*)(sm_raw + 57088);
        for (int u = bx; u < NSPLIT * BS; u += nb) {
            int s = u & 15, b = u >> 4;
            const float4* qlb = (const float4*)&g_qlat[b][0][0];
            for (int i = tid; i < NH * KVL / 4; i += 256) ((float4*)s_qlat)[i] = qlb[i];
            const float4* qpb = (const float4*)&g_qpe[b][0][0];
            for (int i = tid; i < NH * DR / 4; i += 256) ((float4*)s_qpe)[i] = qpb[i];
            if (tid < SPLITROWS) {
                int j = tid;
                int n = g_sel[b][s * SPLITROWS + j];
                float v = g_selval[b][s * SPLITROWS + j];
                bool valid = v > -1e8f;
                const float* cp; const float* kp;
                if (!valid) { cp = g_ckv[b]; kp = g_kr[b]; }
                else {
                    int blk = bt[b * BPS + (n >> 7)];
                    long flat = (long)blk * BLKSZ + (n & 127);
                    if (flat == (long)cidx[b]) { cp = g_ckv[b]; kp = g_kr[b]; }
                    else { cp = kvc + flat * KVL; kp = krc + flat * DR; }
                }
                s_ckvp[j] = cp; s_krp[j] = kp; s_vld[j] = valid ? 1 : 0;
            }
            if (tid < NH) { s_m[tid] = -1e30f; s_l[tid] = 0.f; }
            ull oc0[NH / 2], oc1[NH / 2];
            #pragma unroll
            for (int k = 0; k < NH / 2; k++) { oc0[k] = 0ull; oc1[k] = 0ull; }
            __syncthreads();
            int warp = tid >> 5, lane = tid & 31;
            for (int g = 0; g < SPLITROWS / 8; g++) {
                #pragma unroll
                for (int k = 0; k < 4; k++) {
                    int f = tid + 256 * k;
                    int r = f >> 7, pos = f & 127;
                    ((float4*)&s_kv[r * 512])[pos] = ((const float4*)s_ckvp[g * 8 + r])[pos];
                }
                if (tid < 128) {
                    int r = tid >> 4, pos = tid & 15;
                    ((float4*)&s_kr[r * 64])[pos] = ((const float4*)s_krp[g * 8 + r])[pos];
                }
                __syncthreads();
                {
                    int j = warp;
                    ull acc2[NH];
                    #pragma unroll
                    for (int h = 0; h < NH; h++) acc2[h] = 0ull;
                    #pragma unroll
                    for (int q = 0; q < 4; q++) {
                        ulonglong2 v = *(const ulonglong2*)&s_kv[j * 512 + 4 * (lane + 32 * q)];
                        #pragma unroll
                        for (int h = 0; h < NH; h++) {
                            ulonglong2 ql = *(const ulonglong2*)&s_qlat[h * KVL + 4 * (lane + 32 * q)];
                            acc2[h] = ffma2(v.x, ql.x, acc2[h]);
                            acc2[h] = ffma2(v.y, ql.y, acc2[h]);
                        }
                    }
                    ull kvr = *(const ull*)&s_kr[j * 64 + 2 * lane];
                    float acc[NH];
                    #pragma unroll
                    for (int h = 0; h < NH; h++) {
                        ull qp = *(const ull*)&s_qpe[h * DR + 2 * lane];
                        acc2[h] = ffma2(kvr, qp, acc2[h]);
                        float2 t = funpack2(acc2[h]);
                        acc[h] = t.x + t.y;
                    }
                    #pragma unroll
                    for (int off = 16; off; off >>= 1) {
                        #pragma unroll
                        for (int h = 0; h < NH; h++)
                            acc[h] += __shfl_xor_sync(0xffffffffu, acc[h], off);
                    }
                    if (lane == 0) {
                        bool valid = s_vld[g * 8 + j] != 0;
                        #pragma unroll
                        for (int h = 0; h < NH; h++)
                            s_sc[j * NH + h] = valid ? acc[h] * ATT_SCALE : -1e9f;
                    }
                }
                __syncthreads();
                #pragma unroll
                for (int hh = warp; hh < NH; hh += 8) {
                    float sc = (lane < 8) ? s_sc[lane * NH + hh] : -3.0e38f;
                    float gm = sc;
                    #pragma unroll
                    for (int off = 4; off; off >>= 1) gm = fmaxf(gm, __shfl_xor_sync(0xffffffffu, gm, off));
                    float oldm = s_m[hh];
                    float newm = fmaxf(oldm, gm);
                    float p = (lane < 8) ? __expf(sc - newm) : 0.f;
                    float sl = p;
                    #pragma unroll
                    for (int off = 4; off; off >>= 1) sl += __shfl_xor_sync(0xffffffffu, sl, off);
                    if (lane < 8) s_sc[lane * NH + hh] = p;
                    if (lane == 0) {
                        float fac = __expf(oldm - newm);
                        s_m[hh] = newm;
                        s_l[hh] = s_l[hh] * fac + sl;
                        s_fac[hh] = fac;
                    }
                }
                __syncthreads();
                {
                    const ull* facp = (const ull*)s_fac;
                    #pragma unroll
                    for (int k = 0; k < NH / 2; k++) {
                        ull f = facp[k];
                        oc0[k] = fmul2(oc0[k], f);
                        oc1[k] = fmul2(oc1[k], f);
                    }
                    int c0 = tid, c1 = tid + 256;
                    #pragma unroll
                    for (int j = 0; j < 8; j++) {
                        float va = s_kv[j * 512 + c0];
                        float vb = s_kv[j * 512 + c1];
                        ull vva = fpack2(va, va);
                        ull vvb = fpack2(vb, vb);
                        const ull* pp = (const ull*)&s_sc[j * NH];
                        #pragma unroll
                        for (int k = 0; k < NH / 2; k++) {
                            ull p = pp[k];
                            oc0[k] = ffma2(p, vva, oc0[k]);
                            oc1[k] = ffma2(p, vvb, oc1[k]);
                        }
                    }
                }
                __syncthreads();
            }
            if (tid < NH) { g_m[b][s][tid] = s_m[tid]; g_l[b][s][tid] = s_l[tid]; }
            {
                int c0 = tid, c1 = tid + 256;
                #pragma unroll
                for (int k = 0; k < NH / 2; k++) {
                    float2 a = funpack2(oc0[k]);
                    g_op[b][s][2 * k][c0]     = a.x;
                    g_op[b][s][2 * k + 1][c0] = a.y;
                    float2 c = funpack2(oc1[k]);
                    g_op[b][s][2 * k][c1]     = c.x;
                    g_op[b][s][2 * k + 1][c1] = c.y;
                }
            }
            __syncthreads();
        }
    }
    gsync(5, nb);

    // ===== P6: combine + output projection (float4 reduce) =====
    {
        float* s_olat = (float*)sm_raw;
        float* s_w    = (float*)(sm_raw + 2048);
        float* s_invl = (float*)(sm_raw + 2112);
        for (int u = bx; u < NH * BS; u += nb) {
            int h = u & 15, b = u >> 4;
            if (tid == 0) {
                float M = -1e30f;
                for (int s = 0; s < NSPLIT; s++) M = fmaxf(M, g_m[b][s][h]);
                float L = 0.f;
                for (int s = 0; s < NSPLIT; s++) {
                    float w = __expf(g_m[b][s][h] - M);
                    s_w[s] = w;
                    L += g_l[b][s][h] * w;
                }
                *s_invl = 1.f / L;
            }
            __syncthreads();
            if (tid < 128) {
                int c4 = tid;
                float4 a = make_float4(0.f, 0.f, 0.f, 0.f);
                #pragma unroll
                for (int s = 0; s < NSPLIT; s++) {
                    float4 v = ((const float4*)&g_op[b][s][h][0])[c4];
                    float w = s_w[s];
                    a.x += v.x * w; a.y += v.y * w; a.z += v.z * w; a.w += v.w * w;
                }
                float il = *s_invl;
                a.x *= il; a.y *= il; a.z *= il; a.w *= il;
                ((float4*)s_olat)[c4] = a;
            }
            __syncthreads();
            if (tid < DN) {
                int d = tid;
                const float* wk = w_uk + ((size_t)(h * DN + d)) * KVL;
                float a = 0.f;
                #pragma unroll 8
                for (int c = 0; c < KVL; c += 4) {
                    float4 o4 = *(const float4*)&s_olat[c];
                    float4 w4 = *(const float4*)&wk[c];
                    a += o4.x * w4.x + o4.y * w4.y + o4.z * w4.z + o4.w * w4.w;
                }
                out[b * (NH * DN) + h * DN + d] = a;
            }
            __syncthreads();
        }
    }

    // reset sync state for next graph replay
    __syncthreads();
    if (tid == 0) {
        __threadfence();
        unsigned a = atomicAdd(&g_ack, 1u) + 1;
        if (a == (unsigned)nb) {
            #pragma unroll
            for (int i = 0; i < 8; i++) g_barcnt[i] = 0;
            g_ack = 0;
            __threadfence();
        }
    }
}

// ---------------- launch ----------------
extern "C" void kernel_launch(void* const* d_in, const int* in_sizes, int n_in,
                              void* d_out, int out_size) {
    const float* x            = (const float*)d_in[0];
    const float* w_dq         = (const float*)d_in[1];
    const float* w_uq_qr      = (const float*)d_in[2];
    const float* w_uk         = (const float*)d_in[3];
    const float* w_dkv_kr     = (const float*)d_in[4];
    const float* gamma_cq     = (const float*)d_in[5];
    const float* gamma_ckv    = (const float*)d_in[6];
    const float* sinp         = (const float*)d_in[7];
    const float* cosp         = (const float*)d_in[8];
    const int*   cache_index  = (const int*)d_in[9];
    const float* kv_cache     = (const float*)d_in[10];
    const float* kr_cache     = (const float*)d_in[11];
    const int*   block_table  = (const int*)d_in[12];
    const int*   act_seqs     = (const int*)d_in[13];
    const float* w_idx_qb     = (const float*)d_in[14];
    const float* w_idx_k      = (const float*)d_in[15];
    const float* w_idx_proj   = (const float*)d_in[16];
    const float* in_gamma_k   = (const float*)d_in[17];
    const float* in_beta_k    = (const float*)d_in[18];
    const float* index_k_cache= (const float*)d_in[19];
    float* out = (float*)d_out;

    cudaFuncSetAttribute(k_mega, cudaFuncAttributeMaxDynamicSharedMemorySize, SMSZ);

    int sms = 148, bpm = 0;
    cudaDeviceGetAttribute(&sms, cudaDevAttrMultiProcessorCount, 0);
    cudaOccupancyMaxActiveBlocksPerMultiprocessor(&bpm, k_mega, 256, SMSZ);
    if (bpm < 1) bpm = 1;
    int nb = bpm * sms;
    if (nb > NBMAX) nb = NBMAX;

    k_mega<<<nb, 256, SMSZ>>>(x, w_dq, w_uq_qr, w_uk, w_dkv_kr, gamma_cq, gamma_ckv,
                              sinp, cosp, cache_index, kv_cache, kr_cache, block_table,
                              act_seqs, w_idx_qb, w_idx_k, w_idx_proj, in_gamma_k,
                              in_beta_k, index_k_cache, out, nb);
}